// round 16
// baseline (speedup 1.0000x reference)
#include <cuda_runtime.h>
#include <cuda_fp16.h>
#include <cstdint>

#define NN 100000
#define NE 300000
#define HID 256

// ---- scratch (static device globals; allocation-free) ----
__device__ __half g_h0h[NN * HID];            // h (fp16) ping
__device__ __half g_h1h[NN * HID];            // h (fp16) pong
__device__ __half g_th[NN * HID];             // t = h @ Wmsg_top (fp16)
__device__ __half g_zh[NN * HID];             // z = h @ Wself (fp16)
__device__ __half g_uvh[NN * HID];            // [U | V] (fp16)
__device__ int   g_atype[NN];
__device__ int   g_pv[NN];
__device__ float g_deg[NN];
__device__ int   g_cnt[NN];
__device__ int   g_rowptr[NN + 1];
__device__ int   g_cur[NN];
__device__ int   g_ecol[NE];
__device__ int   g_ebt[NE];
__device__ int   g_bsum[98];
__device__ int   g_boff[98];
__device__ float g_tlogits[11 * 8];
__device__ int   g_tpv[11];
__device__ float g_msgbias[3 * 5 * 256];
__device__ __half2 g_wmsg_h[3 * 128 * 256];   // k-pair packed fp16 weights
__device__ __half2 g_wself_h[3 * 128 * 256];
__device__ __half2 g_bccat_h[128 * 256];

__device__ __forceinline__ void mma_f16(float c[4],
    unsigned a0, unsigned a1, unsigned a2, unsigned a3,
    unsigned b0, unsigned b1)
{
    asm volatile(
        "mma.sync.aligned.m16n8k16.row.col.f32.f16.f16.f32 "
        "{%0,%1,%2,%3}, {%4,%5,%6,%7}, {%8,%9}, {%0,%1,%2,%3};"
        : "+f"(c[0]), "+f"(c[1]), "+f"(c[2]), "+f"(c[3])
        : "r"(a0), "r"(a1), "r"(a2), "r"(a3), "r"(b0), "r"(b1));
}

__device__ __forceinline__ void ldsm4(unsigned r[4], uint32_t addr)
{
    asm volatile(
        "ldmatrix.sync.aligned.m8n8.x4.shared.b16 {%0,%1,%2,%3}, [%4];"
        : "=r"(r[0]), "=r"(r[1]), "=r"(r[2]), "=r"(r[3]) : "r"(addr));
}

__device__ __forceinline__ void cpasync16(void* sptr, const void* g) {
    uint32_t sa = (uint32_t)__cvta_generic_to_shared(sptr);
    asm volatile("cp.async.cg.shared.global [%0], [%1], 16;" :: "r"(sa), "l"(g) : "memory");
}

__device__ __forceinline__ void ld8h(const __half* p, float v[8]) {
    uint4 raw = *(const uint4*)p;
    const __half2* hp = (const __half2*)&raw;
    float2 f;
    f = __half22float2(hp[0]); v[0] = f.x; v[1] = f.y;
    f = __half22float2(hp[1]); v[2] = f.x; v[3] = f.y;
    f = __half22float2(hp[2]); v[4] = f.x; v[5] = f.y;
    f = __half22float2(hp[3]); v[6] = f.x; v[7] = f.y;
}
__device__ __forceinline__ void ld4h(const __half* p, float v[4]) {
    uint2 raw = *(const uint2*)p;
    const __half2* hp = (const __half2*)&raw;
    float2 f;
    f = __half22float2(hp[0]); v[0] = f.x; v[1] = f.y;
    f = __half22float2(hp[1]); v[2] = f.x; v[3] = f.y;
}

// ============================================================
// 64-row fp16 pipelined GEMM: [64 nodes x 256] @ 512 threads.
// A-fragments via ldmatrix.x4; fp16 output.
// ============================================================
#define A_STRIDE 40
#define W_STRIDE 264
#define SMEM_F16 (64 * A_STRIDE * 2 + 2 * 16 * W_STRIDE * 4)

__global__ __launch_bounds__(512, 2) void k_gemm64(
        const __half* __restrict__ hin,
        const __half2* __restrict__ w0, __half* __restrict__ out0,
        const __half2* __restrict__ w1, __half* __restrict__ out1,
        int ksteps, int dual)
{
    extern __shared__ char smraw[];
    __half (*As)[A_STRIDE] = (__half(*)[A_STRIDE])smraw;
    __half2 (*WsA)[W_STRIDE] = (__half2(*)[W_STRIDE])(smraw + 64 * A_STRIDE * 2);
    __half2 (*WsB)[W_STRIDE] = (__half2(*)[W_STRIDE])(smraw + 64 * A_STRIDE * 2 + 16 * W_STRIDE * 4);

    int nb;
    const __half2* wtf;
    __half* outp;
    if (dual) {
        int par = blockIdx.x & 1;
        nb = (blockIdx.x >> 1) * 64;
        wtf  = par ? w1 : w0;
        outp = par ? out1 : out0;
    } else {
        nb = blockIdx.x * 64;
        wtf = w0; outp = out0;
    }

    int tid = threadIdx.x;
    int warp = tid >> 5, lane = tid & 31;
    int n0 = warp * 16;
    const int lr = lane >> 2, lc = lane & 3;
    const int arow = tid >> 3, ah4 = (tid & 7) * 4;
    const int arowi = min(nb + arow, NN - 1);
    // ldmatrix per-lane source row/col
    const int q = lane >> 3, l8 = lane & 7;
    const int rowA = (q & 1) * 8 + l8, colOff = (q >> 1) * 8;
    const uint32_t as_base = (uint32_t)__cvta_generic_to_shared(&As[0][0]);

    float c[4][2][4];
#pragma unroll
    for (int m = 0; m < 4; m++)
#pragma unroll
        for (int n = 0; n < 2; n++)
#pragma unroll
            for (int j = 0; j < 4; j++) c[m][n][j] = 0.f;

    uint2 aNext = *(const uint2*)&hin[(size_t)arowi * HID + ah4];
#pragma unroll
    for (int i = 0; i < 2; i++) {
        int idx = tid + 512 * i;
        int r = idx >> 6, c4 = (idx & 63) * 4;
        cpasync16(&WsA[r][c4], &wtf[(size_t)r * 256 + c4]);
    }
    asm volatile("cp.async.commit_group;" ::: "memory");

    for (int kt = 0; kt < ksteps; kt++) {
        __half2 (*Wcur)[W_STRIDE] = (kt & 1) ? WsB : WsA;
        __half2 (*Wnxt)[W_STRIDE] = (kt & 1) ? WsA : WsB;
        uint2 aCur = aNext;
        __syncthreads();
        bool next = (kt + 1 < ksteps);
        if (next) {
            int kp0 = (kt + 1) * 16;
#pragma unroll
            for (int i = 0; i < 2; i++) {
                int idx = tid + 512 * i;
                int r = idx >> 6, c4 = (idx & 63) * 4;
                cpasync16(&Wnxt[r][c4], &wtf[(size_t)(kp0 + r) * 256 + c4]);
            }
            asm volatile("cp.async.commit_group;" ::: "memory");
            aNext = *(const uint2*)&hin[(size_t)arowi * HID + (kt + 1) * 32 + ah4];
        }
        *(uint2*)&As[arow][ah4] = aCur;
        if (next) asm volatile("cp.async.wait_group 1;" ::: "memory");
        else      asm volatile("cp.async.wait_group 0;" ::: "memory");
        __syncthreads();
#pragma unroll
        for (int ks = 0; ks < 2; ks++) {
            int kb = ks * 16;
            int wb = ks * 8;
            unsigned b[2][2];
#pragma unroll
            for (int n = 0; n < 2; n++) {
                int nc = n0 + n * 8 + lr;
                b[n][0] = *(const unsigned*)&Wcur[wb + lc][nc];
                b[n][1] = *(const unsigned*)&Wcur[wb + lc + 4][nc];
            }
#pragma unroll
            for (int m = 0; m < 4; m++) {
                unsigned a[4];
                ldsm4(a, as_base + (uint32_t)(((m * 16 + rowA) * A_STRIDE
                                               + kb + colOff) * 2));
#pragma unroll
                for (int n = 0; n < 2; n++)
                    mma_f16(c[m][n], a[0], a[1], a[2], a[3], b[n][0], b[n][1]);
            }
        }
    }

    int g = lane >> 2, cc = 2 * (lane & 3);
#pragma unroll
    for (int m = 0; m < 4; m++) {
        int row0 = nb + m * 16 + g;
        int row1 = row0 + 8;
#pragma unroll
        for (int n = 0; n < 2; n++) {
            int col = n0 + n * 8 + cc;
            if (row0 < NN)
                *(__half2*)&outp[(size_t)row0 * HID + col] =
                    __floats2half2_rn(c[m][n][0], c[m][n][1]);
            if (row1 < NN)
                *(__half2*)&outp[(size_t)row1 * HID + col] =
                    __floats2half2_rn(c[m][n][2], c[m][n][3]);
        }
    }
}

// ============================================================
// Prep: type-pred MLP (b0), bond-bias fold (1..15), fp16 weight
// packing (wmsg 16..399, wself 400..783, bccat 784..911), cnt zero
// ============================================================
__global__ void k_prep(const float* __restrict__ atom_emb,
                       const float* __restrict__ vp_w1, const float* __restrict__ vp_b1,
                       const float* __restrict__ vp_w2, const float* __restrict__ vp_b2,
                       const float* __restrict__ wmsg, const float* __restrict__ bmsg,
                       const float* __restrict__ bond_emb,
                       const float* __restrict__ wself, const float* __restrict__ bcw1)
{
    int b = blockIdx.x;
    int tid = threadIdx.x;
    if (b == 0) {
        if (tid >= 11) return;
        int t = tid;
        float z[32];
        for (int j = 0; j < 32; j++) {
            float s = vp_b1[j];
            for (int k = 0; k < 64; k++) s += atom_emb[t * 64 + k] * vp_w1[k * 32 + j];
            z[j] = fmaxf(s, 0.f);
        }
        float best = -1e30f; int bi = 0;
        for (int j = 0; j < 8; j++) {
            float s = vp_b2[j];
            for (int k = 0; k < 32; k++) s += z[k] * vp_w2[k * 8 + j];
            g_tlogits[t * 8 + j] = s;
            if (s > best) { best = s; bi = j; }
        }
        g_tpv[t] = bi + 1;
    } else if (b < 16) {
        int idx = b - 1;
        int l = idx / 5, bt = idx % 5;
        const float* w = wmsg + (size_t)l * 320 * HID;
        float s = bmsg[l * HID + tid];
#pragma unroll 8
        for (int j = 0; j < 64; j++)
            s += bond_emb[bt * 64 + j] * w[(size_t)(256 + j) * HID + tid];
        g_msgbias[(size_t)idx * 256 + tid] = s;
    } else if (b < 400) {
        int i = (b - 16) * 256 + tid;          // over 3*32768
        int l = i >> 15, rest = i & 32767;
        int kp = rest >> 8, n = rest & 255;
        const float* w = wmsg + (size_t)l * 320 * 256;
        g_wmsg_h[i] = __halves2half2(
            __float2half_rn(w[(size_t)(2 * kp) * 256 + n]),
            __float2half_rn(w[(size_t)(2 * kp + 1) * 256 + n]));
    } else if (b < 784) {
        int i = (b - 400) * 256 + tid;
        int l = i >> 15, rest = i & 32767;
        int kp = rest >> 8, n = rest & 255;
        const float* w = wself + (size_t)l * 65536;
        g_wself_h[i] = __halves2half2(
            __float2half_rn(w[(size_t)(2 * kp) * 256 + n]),
            __float2half_rn(w[(size_t)(2 * kp + 1) * 256 + n]));
    } else if (b < 912) {
        int i = (b - 784) * 256 + tid;         // over 128*256
        int kp = i >> 8, n = i & 255;
        float lo = (n < 128) ? bcw1[(size_t)(2 * kp) * 128 + n]
                             : bcw1[(size_t)(256 + 2 * kp) * 128 + (n - 128)];
        float hi = (n < 128) ? bcw1[(size_t)(2 * kp + 1) * 128 + n]
                             : bcw1[(size_t)(256 + 2 * kp + 1) * 128 + (n - 128)];
        g_bccat_h[i] = __halves2half2(__float2half_rn(lo), __float2half_rn(hi));
    } else {
        int i = (b - 912) * 256 + tid;
        if (i < NN) g_cnt[i] = 0;
    }
}

// ============================================================
// Node init: h0 stored as fp16 (only GEMMs consume it)
// ============================================================
__global__ void k_node_init(const float* __restrict__ x,
                            const float* __restrict__ atom_emb,
                            float* __restrict__ out_vlog)
{
    int gid = blockIdx.x * blockDim.x + threadIdx.x;
    int n = gid >> 5, lane = gid & 31;
    if (n >= NN) return;
    int at = (int)x[(size_t)n * 16];
    at = min(max(at, 0), 10);
    int pv = g_tpv[at];
    if (lane == 0) { g_atype[n] = at; g_pv[n] = pv; }
    if (lane < 8) out_vlog[(size_t)n * 8 + lane] = g_tlogits[at * 8 + lane];
#pragma unroll
    for (int r = 0; r < 8; r++) {
        int c = lane + 32 * r;
        float v;
        if (c < 64)      v = atom_emb[at * 64 + c];
        else if (c < 72) v = (c - 64 == pv - 1) ? 1.f : 0.f;
        else             v = 0.f;
        g_h0h[(size_t)n * HID + c] = __float2half_rn(v);
    }
}

// ============================================================
// CSR build
// ============================================================
__global__ void k_count(const int* __restrict__ edge_index)
{
    int e = blockIdx.x * blockDim.x + threadIdx.x;
    if (e < NE) atomicAdd(&g_cnt[edge_index[e]], 1);
}

__global__ void k_scan1()
{
    __shared__ int sh[32];
    int t = threadIdx.x;
    int n = blockIdx.x * 1024 + t;
    int c = (n < NN) ? g_cnt[n] : 0;
#pragma unroll
    for (int o = 16; o > 0; o >>= 1) c += __shfl_down_sync(0xffffffffu, c, o);
    if ((t & 31) == 0) sh[t >> 5] = c;
    __syncthreads();
    if (t < 32) {
        int v = sh[t];
#pragma unroll
        for (int o = 16; o > 0; o >>= 1) v += __shfl_down_sync(0xffffffffu, v, o);
        if (t == 0) g_bsum[blockIdx.x] = v;
    }
}

__global__ void k_scan2()
{
    __shared__ int sh[128];
    int t = threadIdx.x;
    int v = (t < 98) ? g_bsum[t] : 0;
    sh[t] = v;
    __syncthreads();
    for (int off = 1; off < 128; off <<= 1) {
        int u = (t >= off) ? sh[t - off] : 0;
        __syncthreads();
        sh[t] += u;
        __syncthreads();
    }
    if (t < 98) g_boff[t] = sh[t] - v;
    if (t == 97) g_rowptr[NN] = sh[97];
}

__global__ void k_scan3(float* __restrict__ out_viol)
{
    __shared__ int sh[1024];
    int t = threadIdx.x;
    int n = blockIdx.x * 1024 + t;
    int c = (n < NN) ? g_cnt[n] : 0;
    sh[t] = c;
    __syncthreads();
    for (int off = 1; off < 1024; off <<= 1) {
        int u = (t >= off) ? sh[t - off] : 0;
        __syncthreads();
        sh[t] += u;
        __syncthreads();
    }
    if (n < NN) {
        int excl = sh[t] - c + g_boff[blockIdx.x];
        g_rowptr[n] = excl;
        g_cur[n] = excl;
        g_deg[n] = (float)c;
        out_viol[n] = fmaxf((float)c - (float)g_pv[n], 0.f);
    }
}

__global__ void k_scatter(const int* __restrict__ edge_index,
                          const float* __restrict__ edge_attr)
{
    int e = blockIdx.x * blockDim.x + threadIdx.x;
    if (e < NE) {
        int pos = atomicAdd(&g_cur[edge_index[e]], 1);
        g_ecol[pos] = edge_index[NE + e];
        g_ebt[pos] = min(max((int)edge_attr[(size_t)e * 4], 0), 4);
    }
}

// ============================================================
// Aggregation: one WARP per node; fp16 t/z loads, fp32 math;
// writes fp16 h (and fp32 out_h when damp).
// ============================================================
__global__ __launch_bounds__(256, 5) void k_agg(
        const __half* __restrict__ zb, const __half* __restrict__ tb,
        const float* __restrict__ bself, int l, int damp,
        float* __restrict__ outf, __half* __restrict__ outh)
{
    __shared__ float smb[5 * 256];
    __shared__ float sb[256];
    int tid = threadIdx.x;
    {
        const float* mb = g_msgbias + (size_t)l * 1280;
#pragma unroll
        for (int i = 0; i < 5; i++) smb[tid + 256 * i] = mb[tid + 256 * i];
        sb[tid] = bself[tid];
    }
    __syncthreads();

    int node = blockIdx.x * 8 + (tid >> 5);
    int seg = (tid & 31) * 8;
    int s = __ldg(&g_rowptr[node]);
    int e = __ldg(&g_rowptr[node + 1]);

    float a[8];
#pragma unroll
    for (int i = 0; i < 8; i++) a[i] = 0.f;

    int j = s;
    for (; j + 1 < e; j += 2) {
        int c0 = __ldg(&g_ecol[j]),     bt0 = __ldg(&g_ebt[j]);
        int c1 = __ldg(&g_ecol[j + 1]), bt1 = __ldg(&g_ebt[j + 1]);
        float x[8], y[8];
        ld8h(tb + (size_t)c0 * HID + seg, x);
        ld8h(tb + (size_t)c1 * HID + seg, y);
        const float* m0 = smb + bt0 * 256 + seg;
        const float* m1 = smb + bt1 * 256 + seg;
#pragma unroll
        for (int i = 0; i < 8; i++) {
            a[i] += fmaxf(x[i] + m0[i], 0.f);
            a[i] += fmaxf(y[i] + m1[i], 0.f);
        }
    }
    if (j < e) {
        int c0 = __ldg(&g_ecol[j]), bt0 = __ldg(&g_ebt[j]);
        float x[8];
        ld8h(tb + (size_t)c0 * HID + seg, x);
        const float* m0 = smb + bt0 * 256 + seg;
#pragma unroll
        for (int i = 0; i < 8; i++)
            a[i] += fmaxf(x[i] + m0[i], 0.f);
    }

    float z[8];
    ld8h(zb + (size_t)node * HID + seg, z);
    float sc = 1.f;
    if (damp)
        sc = 1.f / (1.f + fmaxf((float)(e - s) - (float)__ldg(&g_pv[node]), 0.f));
    float o[8];
#pragma unroll
    for (int i = 0; i < 8; i++)
        o[i] = fmaxf(z[i] + sb[seg + i] + a[i], 0.f) * sc;
    if (damp) {
        float* op = outf + (size_t)node * HID + seg;
        *(float4*)op = make_float4(o[0], o[1], o[2], o[3]);
        *(float4*)(op + 4) = make_float4(o[4], o[5], o[6], o[7]);
    }
    __half2 hp[4];
    hp[0] = __floats2half2_rn(o[0], o[1]);
    hp[1] = __floats2half2_rn(o[2], o[3]);
    hp[2] = __floats2half2_rn(o[4], o[5]);
    hp[3] = __floats2half2_rn(o[6], o[7]);
    *(uint4*)(outh + (size_t)node * HID + seg) = *(uint4*)hp;
}

// ============================================================
// Bond head: stage1 = gather relu(U[row]+V[col]+pv terms+b1) from
// fp16 uv; stages 2-3 SIMT fp32.
// ============================================================
__global__ __launch_bounds__(256) void k_bc(
        const float* __restrict__ w1, const float* __restrict__ b1,
        const float* __restrict__ w2, const float* __restrict__ b2,
        const float* __restrict__ w3, const float* __restrict__ b3,
        const int* __restrict__ edge_index, float* __restrict__ out_bl)
{
    __shared__ float T1[32][132];
    __shared__ float T2[32][65];
    __shared__ float Ws[32][68];
    __shared__ float s_wpr[128], s_wpc[128], s_bb[128];
    __shared__ int s_row[32], s_col[32], s_atr[32], s_atc[32];
    __shared__ float s_pvr[32], s_pvc[32];
    int tid = threadIdx.x;
    int eb = blockIdx.x * 32;
    if (tid < 32) {
        int e = eb + tid;
        int r = edge_index[e], c = edge_index[NE + e];
        s_row[tid] = r; s_col[tid] = c;
        s_pvr[tid] = (float)g_pv[r]; s_pvc[tid] = (float)g_pv[c];
        s_atr[tid] = g_atype[r];     s_atc[tid] = g_atype[c];
    }
    if (tid < 128) {
        s_wpr[tid] = w1[512 * 128 + tid];
        s_wpc[tid] = w1[513 * 128 + tid];
        s_bb[tid]  = b1[tid];
    }
    __syncthreads();

    int warp = tid >> 5, lane = tid & 31;
    int o = lane * 4;
#pragma unroll
    for (int it = 0; it < 4; it++) {
        int e = warp * 4 + it;
        float u[4], v[4];
        ld4h(g_uvh + (size_t)s_row[e] * 256 + o, u);
        ld4h(g_uvh + (size_t)s_col[e] * 256 + 128 + o, v);
        float pr = s_pvr[e], pc = s_pvc[e];
#pragma unroll
        for (int jj = 0; jj < 4; jj++)
            T1[e][o + jj] = fmaxf(u[jj] + v[jj] + pr * s_wpr[o + jj]
                                  + pc * s_wpc[o + jj] + s_bb[o + jj], 0.f);
    }
    __syncthreads();

    float acc2[2][4];
#pragma unroll
    for (int i = 0; i < 2; i++)
#pragma unroll
        for (int j = 0; j < 4; j++) acc2[i][j] = 0.f;
    const int tx2 = tid & 15, ty2 = tid >> 4;
    for (int kt = 0; kt < 4; kt++) {
        int k0 = kt * 32;
#pragma unroll
        for (int i = 0; i < 2; i++) {
            int idx = tid + 256 * i;
            int k = idx >> 4, c4 = (idx & 15) * 4;
            *(float4*)&Ws[k][c4] = *(const float4*)&w2[(size_t)(k0 + k) * 64 + c4];
        }
        __syncthreads();
#pragma unroll
        for (int kk = 0; kk < 32; kk++) {
            float a0 = T1[ty2 * 2][k0 + kk];
            float a1 = T1[ty2 * 2 + 1][k0 + kk];
            float4 w = *(const float4*)&Ws[kk][tx2 * 4];
            acc2[0][0] += a0 * w.x; acc2[0][1] += a0 * w.y;
            acc2[0][2] += a0 * w.z; acc2[0][3] += a0 * w.w;
            acc2[1][0] += a1 * w.x; acc2[1][1] += a1 * w.y;
            acc2[1][2] += a1 * w.z; acc2[1][3] += a1 * w.w;
        }
        __syncthreads();
    }
#pragma unroll
    for (int i = 0; i < 2; i++) {
        int e = ty2 * 2 + i;
#pragma unroll
        for (int j = 0; j < 4; j++) {
            int oo = tx2 * 4 + j;
            T2[e][oo] = fmaxf(acc2[i][j] + __ldg(&b2[oo]), 0.f);
        }
    }
    __syncthreads();

    if (tid < 128) {
        int e = tid >> 2, oo = tid & 3;
        float s = __ldg(&b3[oo]);
#pragma unroll
        for (int k = 0; k < 64; k++) s += T2[e][k] * __ldg(&w3[k * 4 + oo]);
        int ar = s_atr[e], ac = s_atc[e];
        float pr = s_pvr[e], pc = s_pvc[e];
        bool hal = (ar == 4) || (ar == 5) || (ac == 4) || (ac == 5);
        bool l1 = (pr <= 1.f) || (pc <= 1.f);
        bool l2 = (pr <= 2.f) || (pc <= 2.f);
        float pen = 0.f;
        if (oo >= 1) { if (hal) pen -= 100.f; if (l1) pen -= 50.f; }
        if (oo == 2) { if (l2) pen -= 50.f; }
        out_bl[(size_t)(eb + e) * 4 + oo] = s + pen;
    }
}

// ============================================================
// Chem head (SIMT; fp32 on out_h)
// ============================================================
__global__ __launch_bounds__(256) void k_cp(const float* __restrict__ hfin,
        const float* __restrict__ w1, const float* __restrict__ b1,
        const float* __restrict__ w2, const float* __restrict__ b2,
        float* __restrict__ out_cp)
{
    __shared__ float As[32][36];
    __shared__ float Ws[32][132];
    __shared__ float T1[32][129];
    int tid = threadIdx.x;
    int nb = blockIdx.x * 32;
    float acc[4][4];
#pragma unroll
    for (int i = 0; i < 4; i++)
#pragma unroll
        for (int j = 0; j < 4; j++) acc[i][j] = 0.f;
    const int tx = tid & 31, ty = tid >> 5;
    const int arow = tid >> 3, ac4 = (tid & 7) * 4;
    for (int kt = 0; kt < 8; kt++) {
        int k0 = kt * 32;
        *(float4*)&As[arow][ac4] =
            *(const float4*)&hfin[(size_t)(nb + arow) * HID + k0 + ac4];
#pragma unroll
        for (int i = 0; i < 4; i++) {
            int idx = tid + 256 * i;
            int k = idx >> 5, c4 = (idx & 31) * 4;
            *(float4*)&Ws[k][c4] = *(const float4*)&w1[(size_t)(k0 + k) * 128 + c4];
        }
        __syncthreads();
#pragma unroll
        for (int kk = 0; kk < 32; kk++) {
            float a[4];
#pragma unroll
            for (int i = 0; i < 4; i++) a[i] = As[ty * 4 + i][kk];
            float4 w = *(const float4*)&Ws[kk][tx * 4];
#pragma unroll
            for (int i = 0; i < 4; i++) {
                acc[i][0] += a[i] * w.x; acc[i][1] += a[i] * w.y;
                acc[i][2] += a[i] * w.z; acc[i][3] += a[i] * w.w;
            }
        }
        __syncthreads();
    }
#pragma unroll
    for (int i = 0; i < 4; i++) {
        int e = ty * 4 + i;
#pragma unroll
        for (int j = 0; j < 4; j++) {
            int o = tx * 4 + j;
            T1[e][o] = fmaxf(acc[i][j] + __ldg(&b1[o]), 0.f);
        }
    }
    __syncthreads();

    float acc2[4] = {0.f, 0.f, 0.f, 0.f};
    const int tx2 = tid & 7, ty2 = tid >> 3;
    for (int kt = 0; kt < 4; kt++) {
        int k0 = kt * 32;
        {
            int k = tid >> 3, c4 = (tid & 7) * 4;
            *(float4*)&Ws[k][c4] = *(const float4*)&w2[(size_t)(k0 + k) * 32 + c4];
        }
        __syncthreads();
#pragma unroll
        for (int kk = 0; kk < 32; kk++) {
            float a = T1[ty2][k0 + kk];
            float4 w = *(const float4*)&Ws[kk][tx2 * 4];
            acc2[0] += a * w.x; acc2[1] += a * w.y;
            acc2[2] += a * w.z; acc2[3] += a * w.w;
        }
        __syncthreads();
    }
#pragma unroll
    for (int j = 0; j < 4; j++) {
        int o = tx2 * 4 + j;
        out_cp[(size_t)(nb + ty2) * 32 + o] = acc2[j] + __ldg(&b2[o]);
    }
}

// ============================================================
extern "C" void kernel_launch(void* const* d_in, const int* in_sizes, int n_in,
                              void* d_out, int out_size)
{
    (void)in_sizes; (void)n_in; (void)out_size;
    const float* x         = (const float*)d_in[0];
    const float* edge_attr = (const float*)d_in[1];
    const float* atom_emb  = (const float*)d_in[2];
    const float* bond_emb  = (const float*)d_in[3];
    const float* vp_w1     = (const float*)d_in[4];
    const float* vp_b1     = (const float*)d_in[5];
    const float* vp_w2     = (const float*)d_in[6];
    const float* vp_b2     = (const float*)d_in[7];
    const float* gnn_wself = (const float*)d_in[8];
    const float* gnn_bself = (const float*)d_in[9];
    const float* gnn_wmsg  = (const float*)d_in[10];
    const float* gnn_bmsg  = (const float*)d_in[11];
    const float* bc_w1     = (const float*)d_in[12];
    const float* bc_b1     = (const float*)d_in[13];
    const float* bc_w2     = (const float*)d_in[14];
    const float* bc_b2     = (const float*)d_in[15];
    const float* bc_w3     = (const float*)d_in[16];
    const float* bc_b3     = (const float*)d_in[17];
    const float* cp_w1     = (const float*)d_in[18];
    const float* cp_b1     = (const float*)d_in[19];
    const float* cp_w2     = (const float*)d_in[20];
    const float* cp_b2     = (const float*)d_in[21];
    const int* edge_index  = (const int*)d_in[22];

    float* out      = (float*)d_out;
    float* out_h    = out;                                 // [N,256]
    float* out_cp   = out_h    + (size_t)NN * HID;         // [N,32]
    float* out_vlog = out_cp   + (size_t)NN * 32;          // [N,8]
    float* out_bl   = out_vlog + (size_t)NN * 8;           // [E,4]
    float* out_viol = out_bl   + (size_t)NE * 4;           // [N]

    cudaFuncSetAttribute(k_gemm64, cudaFuncAttributeMaxDynamicSharedMemorySize, SMEM_F16);

    __half *p_h0h, *p_h1h, *p_th, *p_zh, *p_uvh;
    __half2 *p_wmsg, *p_wself, *p_bccat;
    cudaGetSymbolAddress((void**)&p_h0h,   g_h0h);
    cudaGetSymbolAddress((void**)&p_h1h,   g_h1h);
    cudaGetSymbolAddress((void**)&p_th,    g_th);
    cudaGetSymbolAddress((void**)&p_zh,    g_zh);
    cudaGetSymbolAddress((void**)&p_uvh,   g_uvh);
    cudaGetSymbolAddress((void**)&p_wmsg,  g_wmsg_h);
    cudaGetSymbolAddress((void**)&p_wself, g_wself_h);
    cudaGetSymbolAddress((void**)&p_bccat, g_bccat_h);

    const int GB = (NN + 63) / 64;            // 1563 blocks per matrix

    k_prep<<<1303, 256>>>(atom_emb, vp_w1, vp_b1, vp_w2, vp_b2,
                          gnn_wmsg, gnn_bmsg, bond_emb, gnn_wself, bc_w1);
    k_node_init<<<(NN * 32 + 255) / 256, 256>>>(x, atom_emb, out_vlog);
    k_count<<<(NE + 255) / 256, 256>>>(edge_index);
    // layer-0 dual GEMM: t0 = h0@Wmsg0, z0 = h0@Wself0   (captured by ncu)
    k_gemm64<<<2 * GB, 512, SMEM_F16>>>(p_h0h, p_wmsg, p_th, p_wself, p_zh, 3, 1);
    k_scan1<<<98, 1024>>>();
    k_scan2<<<1, 128>>>();
    k_scan3<<<98, 1024>>>(out_viol);
    k_scatter<<<(NE + 255) / 256, 256>>>(edge_index, edge_attr);

    // layer 0 aggregate: h1 = agg(z0, t0)
    k_agg<<<NN / 8, 256>>>(p_zh, p_th, gnn_bself + 0 * HID, 0, 0, out_h, p_h1h);
    // layer 1
    k_gemm64<<<2 * GB, 512, SMEM_F16>>>(p_h1h, p_wmsg + 32768, p_th,
                                        p_wself + 32768, p_zh, 8, 1);
    k_agg<<<NN / 8, 256>>>(p_zh, p_th, gnn_bself + 1 * HID, 1, 0, out_h, p_h0h);
    // layer 2 (damped: writes fp32 out_h + fp16 copy for UV GEMM)
    k_gemm64<<<2 * GB, 512, SMEM_F16>>>(p_h0h, p_wmsg + 2 * 32768, p_th,
                                        p_wself + 2 * 32768, p_zh, 8, 1);
    k_agg<<<NN / 8, 256>>>(p_zh, p_th, gnn_bself + 2 * HID, 2, 1, out_h, p_h1h);

    // bond head precompute: UV = h_final(fp16) @ [W1top|W1bot]
    k_gemm64<<<GB, 512, SMEM_F16>>>(p_h1h, p_bccat, p_uvh, nullptr, nullptr, 8, 0);

    k_bc<<<NE / 32, 256>>>(bc_w1, bc_b1, bc_w2, bc_b2, bc_w3, bc_b3,
                           edge_index, out_bl);
    k_cp<<<NN / 32, 256>>>(out_h, cp_w1, cp_b1, cp_w2, cp_b2, out_cp);
}

// round 17
// speedup vs baseline: 1.5145x; 1.5145x over previous
#include <cuda_runtime.h>
#include <cuda_fp16.h>
#include <cstdint>

#define NN 100000
#define NE 300000
#define HID 256

// ---- scratch (static device globals; allocation-free) ----
__device__ __half g_h0h[NN * HID];            // h (fp16) ping
__device__ __half g_h1h[NN * HID];            // h (fp16) pong
__device__ __half g_th[NN * HID];             // t = h @ Wmsg_top (fp16)
__device__ __half g_zh[NN * HID];             // z = h @ Wself (fp16)
__device__ __half g_uvh[NN * HID];            // [U | V] (fp16)
__device__ int   g_atype[NN];
__device__ int   g_pv[NN];
__device__ float g_deg[NN];
__device__ int   g_cnt[NN];
__device__ int   g_rowptr[NN + 1];
__device__ int   g_cur[NN];
__device__ int   g_ecol[NE];
__device__ int   g_ebt[NE];
__device__ int   g_bsum[98];
__device__ int   g_boff[98];
__device__ float g_tlogits[11 * 8];
__device__ int   g_tpv[11];
__device__ float g_msgbias[3 * 5 * 256];
__device__ __half2 g_wmsg_h[3 * 128 * 256];   // k-pair packed fp16 weights
__device__ __half2 g_wself_h[3 * 128 * 256];
__device__ __half2 g_bccat_h[128 * 256];

__device__ __forceinline__ void mma_f16(float c[4],
    unsigned a0, unsigned a1, unsigned a2, unsigned a3,
    unsigned b0, unsigned b1)
{
    asm volatile(
        "mma.sync.aligned.m16n8k16.row.col.f32.f16.f16.f32 "
        "{%0,%1,%2,%3}, {%4,%5,%6,%7}, {%8,%9}, {%0,%1,%2,%3};"
        : "+f"(c[0]), "+f"(c[1]), "+f"(c[2]), "+f"(c[3])
        : "r"(a0), "r"(a1), "r"(a2), "r"(a3), "r"(b0), "r"(b1));
}

__device__ __forceinline__ void cpasync16(void* sptr, const void* g) {
    uint32_t sa = (uint32_t)__cvta_generic_to_shared(sptr);
    asm volatile("cp.async.cg.shared.global [%0], [%1], 16;" :: "r"(sa), "l"(g) : "memory");
}

__device__ __forceinline__ void ld8h(const __half* p, float v[8]) {
    uint4 raw = *(const uint4*)p;
    const __half2* hp = (const __half2*)&raw;
    float2 f;
    f = __half22float2(hp[0]); v[0] = f.x; v[1] = f.y;
    f = __half22float2(hp[1]); v[2] = f.x; v[3] = f.y;
    f = __half22float2(hp[2]); v[4] = f.x; v[5] = f.y;
    f = __half22float2(hp[3]); v[6] = f.x; v[7] = f.y;
}
__device__ __forceinline__ void ld4h(const __half* p, float v[4]) {
    uint2 raw = *(const uint2*)p;
    const __half2* hp = (const __half2*)&raw;
    float2 f;
    f = __half22float2(hp[0]); v[0] = f.x; v[1] = f.y;
    f = __half22float2(hp[1]); v[2] = f.x; v[3] = f.y;
}

// ============================================================
// 64-row fp16 pipelined GEMM: [64 nodes x 256] @ 512 threads.
// Scalar-LDS A-fragments (R15 style); fp16 output.
// ============================================================
#define A_STRIDE 40
#define W_STRIDE 264
#define SMEM_F16 (64 * A_STRIDE * 2 + 2 * 16 * W_STRIDE * 4)

__global__ __launch_bounds__(512, 2) void k_gemm64(
        const __half* __restrict__ hin,
        const __half2* __restrict__ w0, __half* __restrict__ out0,
        const __half2* __restrict__ w1, __half* __restrict__ out1,
        int ksteps, int dual)
{
    extern __shared__ char smraw[];
    __half (*As)[A_STRIDE] = (__half(*)[A_STRIDE])smraw;
    __half2 (*WsA)[W_STRIDE] = (__half2(*)[W_STRIDE])(smraw + 64 * A_STRIDE * 2);
    __half2 (*WsB)[W_STRIDE] = (__half2(*)[W_STRIDE])(smraw + 64 * A_STRIDE * 2 + 16 * W_STRIDE * 4);

    int nb;
    const __half2* wtf;
    __half* outp;
    if (dual) {
        int par = blockIdx.x & 1;
        nb = (blockIdx.x >> 1) * 64;
        wtf  = par ? w1 : w0;
        outp = par ? out1 : out0;
    } else {
        nb = blockIdx.x * 64;
        wtf = w0; outp = out0;
    }

    int tid = threadIdx.x;
    int warp = tid >> 5, lane = tid & 31;
    int n0 = warp * 16;
    const int lr = lane >> 2, lc = lane & 3;
    const int arow = tid >> 3, ah4 = (tid & 7) * 4;
    const int arowi = min(nb + arow, NN - 1);

    float c[4][2][4];
#pragma unroll
    for (int m = 0; m < 4; m++)
#pragma unroll
        for (int n = 0; n < 2; n++)
#pragma unroll
            for (int j = 0; j < 4; j++) c[m][n][j] = 0.f;

    uint2 aNext = *(const uint2*)&hin[(size_t)arowi * HID + ah4];
#pragma unroll
    for (int i = 0; i < 2; i++) {
        int idx = tid + 512 * i;
        int r = idx >> 6, c4 = (idx & 63) * 4;
        cpasync16(&WsA[r][c4], &wtf[(size_t)r * 256 + c4]);
    }
    asm volatile("cp.async.commit_group;" ::: "memory");

    for (int kt = 0; kt < ksteps; kt++) {
        __half2 (*Wcur)[W_STRIDE] = (kt & 1) ? WsB : WsA;
        __half2 (*Wnxt)[W_STRIDE] = (kt & 1) ? WsA : WsB;
        uint2 aCur = aNext;
        __syncthreads();
        bool next = (kt + 1 < ksteps);
        if (next) {
            int kp0 = (kt + 1) * 16;
#pragma unroll
            for (int i = 0; i < 2; i++) {
                int idx = tid + 512 * i;
                int r = idx >> 6, c4 = (idx & 63) * 4;
                cpasync16(&Wnxt[r][c4], &wtf[(size_t)(kp0 + r) * 256 + c4]);
            }
            asm volatile("cp.async.commit_group;" ::: "memory");
            aNext = *(const uint2*)&hin[(size_t)arowi * HID + (kt + 1) * 32 + ah4];
        }
        *(uint2*)&As[arow][ah4] = aCur;
        if (next) asm volatile("cp.async.wait_group 1;" ::: "memory");
        else      asm volatile("cp.async.wait_group 0;" ::: "memory");
        __syncthreads();
#pragma unroll
        for (int ks = 0; ks < 2; ks++) {
            int kb = ks * 16;                   // A half-col base
            int wb = ks * 8;                    // W kp-row base
            unsigned b[2][2];
#pragma unroll
            for (int n = 0; n < 2; n++) {
                int nc = n0 + n * 8 + lr;
                b[n][0] = *(const unsigned*)&Wcur[wb + lc][nc];
                b[n][1] = *(const unsigned*)&Wcur[wb + lc + 4][nc];
            }
#pragma unroll
            for (int m = 0; m < 4; m++) {
                int r = m * 16 + lr;
                unsigned a0 = *(const unsigned*)&As[r][kb + 2 * lc];
                unsigned a1 = *(const unsigned*)&As[r + 8][kb + 2 * lc];
                unsigned a2 = *(const unsigned*)&As[r][kb + 2 * lc + 8];
                unsigned a3 = *(const unsigned*)&As[r + 8][kb + 2 * lc + 8];
#pragma unroll
                for (int n = 0; n < 2; n++)
                    mma_f16(c[m][n], a0, a1, a2, a3, b[n][0], b[n][1]);
            }
        }
    }

    int g = lane >> 2, cc = 2 * (lane & 3);
#pragma unroll
    for (int m = 0; m < 4; m++) {
        int row0 = nb + m * 16 + g;
        int row1 = row0 + 8;
#pragma unroll
        for (int n = 0; n < 2; n++) {
            int col = n0 + n * 8 + cc;
            if (row0 < NN)
                *(__half2*)&outp[(size_t)row0 * HID + col] =
                    __floats2half2_rn(c[m][n][0], c[m][n][1]);
            if (row1 < NN)
                *(__half2*)&outp[(size_t)row1 * HID + col] =
                    __floats2half2_rn(c[m][n][2], c[m][n][3]);
        }
    }
}

// ============================================================
// Prep: type-pred MLP (b0), bond-bias fold (1..15), fp16 weight
// packing (wmsg 16..399, wself 400..783, bccat 784..911), cnt zero
// ============================================================
__global__ void k_prep(const float* __restrict__ atom_emb,
                       const float* __restrict__ vp_w1, const float* __restrict__ vp_b1,
                       const float* __restrict__ vp_w2, const float* __restrict__ vp_b2,
                       const float* __restrict__ wmsg, const float* __restrict__ bmsg,
                       const float* __restrict__ bond_emb,
                       const float* __restrict__ wself, const float* __restrict__ bcw1)
{
    int b = blockIdx.x;
    int tid = threadIdx.x;
    if (b == 0) {
        if (tid >= 11) return;
        int t = tid;
        float z[32];
        for (int j = 0; j < 32; j++) {
            float s = vp_b1[j];
            for (int k = 0; k < 64; k++) s += atom_emb[t * 64 + k] * vp_w1[k * 32 + j];
            z[j] = fmaxf(s, 0.f);
        }
        float best = -1e30f; int bi = 0;
        for (int j = 0; j < 8; j++) {
            float s = vp_b2[j];
            for (int k = 0; k < 32; k++) s += z[k] * vp_w2[k * 8 + j];
            g_tlogits[t * 8 + j] = s;
            if (s > best) { best = s; bi = j; }
        }
        g_tpv[t] = bi + 1;
    } else if (b < 16) {
        int idx = b - 1;
        int l = idx / 5, bt = idx % 5;
        const float* w = wmsg + (size_t)l * 320 * HID;
        float s = bmsg[l * HID + tid];
#pragma unroll 8
        for (int j = 0; j < 64; j++)
            s += bond_emb[bt * 64 + j] * w[(size_t)(256 + j) * HID + tid];
        g_msgbias[(size_t)idx * 256 + tid] = s;
    } else if (b < 400) {
        int i = (b - 16) * 256 + tid;          // over 3*32768
        int l = i >> 15, rest = i & 32767;
        int kp = rest >> 8, n = rest & 255;
        const float* w = wmsg + (size_t)l * 320 * 256;
        g_wmsg_h[i] = __halves2half2(
            __float2half_rn(w[(size_t)(2 * kp) * 256 + n]),
            __float2half_rn(w[(size_t)(2 * kp + 1) * 256 + n]));
    } else if (b < 784) {
        int i = (b - 400) * 256 + tid;
        int l = i >> 15, rest = i & 32767;
        int kp = rest >> 8, n = rest & 255;
        const float* w = wself + (size_t)l * 65536;
        g_wself_h[i] = __halves2half2(
            __float2half_rn(w[(size_t)(2 * kp) * 256 + n]),
            __float2half_rn(w[(size_t)(2 * kp + 1) * 256 + n]));
    } else if (b < 912) {
        int i = (b - 784) * 256 + tid;         // over 128*256
        int kp = i >> 8, n = i & 255;
        float lo = (n < 128) ? bcw1[(size_t)(2 * kp) * 128 + n]
                             : bcw1[(size_t)(256 + 2 * kp) * 128 + (n - 128)];
        float hi = (n < 128) ? bcw1[(size_t)(2 * kp + 1) * 128 + n]
                             : bcw1[(size_t)(256 + 2 * kp + 1) * 128 + (n - 128)];
        g_bccat_h[i] = __halves2half2(__float2half_rn(lo), __float2half_rn(hi));
    } else {
        int i = (b - 912) * 256 + tid;
        if (i < NN) g_cnt[i] = 0;
    }
}

// ============================================================
// Node init: h0 stored as fp16 (only GEMMs consume it)
// ============================================================
__global__ void k_node_init(const float* __restrict__ x,
                            const float* __restrict__ atom_emb,
                            float* __restrict__ out_vlog)
{
    int gid = blockIdx.x * blockDim.x + threadIdx.x;
    int n = gid >> 5, lane = gid & 31;
    if (n >= NN) return;
    int at = (int)x[(size_t)n * 16];
    at = min(max(at, 0), 10);
    int pv = g_tpv[at];
    if (lane == 0) { g_atype[n] = at; g_pv[n] = pv; }
    if (lane < 8) out_vlog[(size_t)n * 8 + lane] = g_tlogits[at * 8 + lane];
#pragma unroll
    for (int r = 0; r < 8; r++) {
        int c = lane + 32 * r;
        float v;
        if (c < 64)      v = atom_emb[at * 64 + c];
        else if (c < 72) v = (c - 64 == pv - 1) ? 1.f : 0.f;
        else             v = 0.f;
        g_h0h[(size_t)n * HID + c] = __float2half_rn(v);
    }
}

// ============================================================
// CSR build
// ============================================================
__global__ void k_count(const int* __restrict__ edge_index)
{
    int e = blockIdx.x * blockDim.x + threadIdx.x;
    if (e < NE) atomicAdd(&g_cnt[edge_index[e]], 1);
}

__global__ void k_scan1()
{
    __shared__ int sh[32];
    int t = threadIdx.x;
    int n = blockIdx.x * 1024 + t;
    int c = (n < NN) ? g_cnt[n] : 0;
#pragma unroll
    for (int o = 16; o > 0; o >>= 1) c += __shfl_down_sync(0xffffffffu, c, o);
    if ((t & 31) == 0) sh[t >> 5] = c;
    __syncthreads();
    if (t < 32) {
        int v = sh[t];
#pragma unroll
        for (int o = 16; o > 0; o >>= 1) v += __shfl_down_sync(0xffffffffu, v, o);
        if (t == 0) g_bsum[blockIdx.x] = v;
    }
}

__global__ void k_scan2()
{
    __shared__ int sh[128];
    int t = threadIdx.x;
    int v = (t < 98) ? g_bsum[t] : 0;
    sh[t] = v;
    __syncthreads();
    for (int off = 1; off < 128; off <<= 1) {
        int u = (t >= off) ? sh[t - off] : 0;
        __syncthreads();
        sh[t] += u;
        __syncthreads();
    }
    if (t < 98) g_boff[t] = sh[t] - v;
    if (t == 97) g_rowptr[NN] = sh[97];
}

__global__ void k_scan3(float* __restrict__ out_viol)
{
    __shared__ int sh[1024];
    int t = threadIdx.x;
    int n = blockIdx.x * 1024 + t;
    int c = (n < NN) ? g_cnt[n] : 0;
    sh[t] = c;
    __syncthreads();
    for (int off = 1; off < 1024; off <<= 1) {
        int u = (t >= off) ? sh[t - off] : 0;
        __syncthreads();
        sh[t] += u;
        __syncthreads();
    }
    if (n < NN) {
        int excl = sh[t] - c + g_boff[blockIdx.x];
        g_rowptr[n] = excl;
        g_cur[n] = excl;
        g_deg[n] = (float)c;
        out_viol[n] = fmaxf((float)c - (float)g_pv[n], 0.f);
    }
}

__global__ void k_scatter(const int* __restrict__ edge_index,
                          const float* __restrict__ edge_attr)
{
    int e = blockIdx.x * blockDim.x + threadIdx.x;
    if (e < NE) {
        int pos = atomicAdd(&g_cur[edge_index[e]], 1);
        g_ecol[pos] = edge_index[NE + e];
        g_ebt[pos] = min(max((int)edge_attr[(size_t)e * 4], 0), 4);
    }
}

// ============================================================
// Aggregation: one WARP per node; fp16 t/z loads, fp32 math;
// writes fp16 h (and fp32 out_h when damp).
// ============================================================
__global__ __launch_bounds__(256, 5) void k_agg(
        const __half* __restrict__ zb, const __half* __restrict__ tb,
        const float* __restrict__ bself, int l, int damp,
        float* __restrict__ outf, __half* __restrict__ outh)
{
    __shared__ float smb[5 * 256];
    __shared__ float sb[256];
    int tid = threadIdx.x;
    {
        const float* mb = g_msgbias + (size_t)l * 1280;
#pragma unroll
        for (int i = 0; i < 5; i++) smb[tid + 256 * i] = mb[tid + 256 * i];
        sb[tid] = bself[tid];
    }
    __syncthreads();

    int node = blockIdx.x * 8 + (tid >> 5);
    int seg = (tid & 31) * 8;
    int s = __ldg(&g_rowptr[node]);
    int e = __ldg(&g_rowptr[node + 1]);

    float a[8];
#pragma unroll
    for (int i = 0; i < 8; i++) a[i] = 0.f;

    int j = s;
    for (; j + 1 < e; j += 2) {
        int c0 = __ldg(&g_ecol[j]),     bt0 = __ldg(&g_ebt[j]);
        int c1 = __ldg(&g_ecol[j + 1]), bt1 = __ldg(&g_ebt[j + 1]);
        float x[8], y[8];
        ld8h(tb + (size_t)c0 * HID + seg, x);
        ld8h(tb + (size_t)c1 * HID + seg, y);
        const float* m0 = smb + bt0 * 256 + seg;
        const float* m1 = smb + bt1 * 256 + seg;
#pragma unroll
        for (int i = 0; i < 8; i++) {
            a[i] += fmaxf(x[i] + m0[i], 0.f);
            a[i] += fmaxf(y[i] + m1[i], 0.f);
        }
    }
    if (j < e) {
        int c0 = __ldg(&g_ecol[j]), bt0 = __ldg(&g_ebt[j]);
        float x[8];
        ld8h(tb + (size_t)c0 * HID + seg, x);
        const float* m0 = smb + bt0 * 256 + seg;
#pragma unroll
        for (int i = 0; i < 8; i++)
            a[i] += fmaxf(x[i] + m0[i], 0.f);
    }

    float z[8];
    ld8h(zb + (size_t)node * HID + seg, z);
    float sc = 1.f;
    if (damp)
        sc = 1.f / (1.f + fmaxf((float)(e - s) - (float)__ldg(&g_pv[node]), 0.f));
    float o[8];
#pragma unroll
    for (int i = 0; i < 8; i++)
        o[i] = fmaxf(z[i] + sb[seg + i] + a[i], 0.f) * sc;
    if (damp) {
        float* op = outf + (size_t)node * HID + seg;
        *(float4*)op = make_float4(o[0], o[1], o[2], o[3]);
        *(float4*)(op + 4) = make_float4(o[4], o[5], o[6], o[7]);
    }
    __half2 hp[4];
    hp[0] = __floats2half2_rn(o[0], o[1]);
    hp[1] = __floats2half2_rn(o[2], o[3]);
    hp[2] = __floats2half2_rn(o[4], o[5]);
    hp[3] = __floats2half2_rn(o[6], o[7]);
    *(uint4*)(outh + (size_t)node * HID + seg) = *(uint4*)hp;
}

// ============================================================
// Bond head: stage1 = gather relu(U[row]+V[col]+pv terms+b1) from
// fp16 uv; stages 2-3 SIMT fp32.
// ============================================================
__global__ __launch_bounds__(256) void k_bc(
        const float* __restrict__ w1, const float* __restrict__ b1,
        const float* __restrict__ w2, const float* __restrict__ b2,
        const float* __restrict__ w3, const float* __restrict__ b3,
        const int* __restrict__ edge_index, float* __restrict__ out_bl)
{
    __shared__ float T1[32][132];
    __shared__ float T2[32][65];
    __shared__ float Ws[32][68];
    __shared__ float s_wpr[128], s_wpc[128], s_bb[128];
    __shared__ int s_row[32], s_col[32], s_atr[32], s_atc[32];
    __shared__ float s_pvr[32], s_pvc[32];
    int tid = threadIdx.x;
    int eb = blockIdx.x * 32;
    if (tid < 32) {
        int e = eb + tid;
        int r = edge_index[e], c = edge_index[NE + e];
        s_row[tid] = r; s_col[tid] = c;
        s_pvr[tid] = (float)g_pv[r]; s_pvc[tid] = (float)g_pv[c];
        s_atr[tid] = g_atype[r];     s_atc[tid] = g_atype[c];
    }
    if (tid < 128) {
        s_wpr[tid] = w1[512 * 128 + tid];
        s_wpc[tid] = w1[513 * 128 + tid];
        s_bb[tid]  = b1[tid];
    }
    __syncthreads();

    int warp = tid >> 5, lane = tid & 31;
    int o = lane * 4;
#pragma unroll
    for (int it = 0; it < 4; it++) {
        int e = warp * 4 + it;
        float u[4], v[4];
        ld4h(g_uvh + (size_t)s_row[e] * 256 + o, u);
        ld4h(g_uvh + (size_t)s_col[e] * 256 + 128 + o, v);
        float pr = s_pvr[e], pc = s_pvc[e];
#pragma unroll
        for (int jj = 0; jj < 4; jj++)
            T1[e][o + jj] = fmaxf(u[jj] + v[jj] + pr * s_wpr[o + jj]
                                  + pc * s_wpc[o + jj] + s_bb[o + jj], 0.f);
    }
    __syncthreads();

    float acc2[2][4];
#pragma unroll
    for (int i = 0; i < 2; i++)
#pragma unroll
        for (int j = 0; j < 4; j++) acc2[i][j] = 0.f;
    const int tx2 = tid & 15, ty2 = tid >> 4;
    for (int kt = 0; kt < 4; kt++) {
        int k0 = kt * 32;
#pragma unroll
        for (int i = 0; i < 2; i++) {
            int idx = tid + 256 * i;
            int k = idx >> 4, c4 = (idx & 15) * 4;
            *(float4*)&Ws[k][c4] = *(const float4*)&w2[(size_t)(k0 + k) * 64 + c4];
        }
        __syncthreads();
#pragma unroll
        for (int kk = 0; kk < 32; kk++) {
            float a0 = T1[ty2 * 2][k0 + kk];
            float a1 = T1[ty2 * 2 + 1][k0 + kk];
            float4 w = *(const float4*)&Ws[kk][tx2 * 4];
            acc2[0][0] += a0 * w.x; acc2[0][1] += a0 * w.y;
            acc2[0][2] += a0 * w.z; acc2[0][3] += a0 * w.w;
            acc2[1][0] += a1 * w.x; acc2[1][1] += a1 * w.y;
            acc2[1][2] += a1 * w.z; acc2[1][3] += a1 * w.w;
        }
        __syncthreads();
    }
#pragma unroll
    for (int i = 0; i < 2; i++) {
        int e = ty2 * 2 + i;
#pragma unroll
        for (int j = 0; j < 4; j++) {
            int oo = tx2 * 4 + j;
            T2[e][oo] = fmaxf(acc2[i][j] + __ldg(&b2[oo]), 0.f);
        }
    }
    __syncthreads();

    if (tid < 128) {
        int e = tid >> 2, oo = tid & 3;
        float s = __ldg(&b3[oo]);
#pragma unroll
        for (int k = 0; k < 64; k++) s += T2[e][k] * __ldg(&w3[k * 4 + oo]);
        int ar = s_atr[e], ac = s_atc[e];
        float pr = s_pvr[e], pc = s_pvc[e];
        bool hal = (ar == 4) || (ar == 5) || (ac == 4) || (ac == 5);
        bool l1 = (pr <= 1.f) || (pc <= 1.f);
        bool l2 = (pr <= 2.f) || (pc <= 2.f);
        float pen = 0.f;
        if (oo >= 1) { if (hal) pen -= 100.f; if (l1) pen -= 50.f; }
        if (oo == 2) { if (l2) pen -= 50.f; }
        out_bl[(size_t)(eb + e) * 4 + oo] = s + pen;
    }
}

// ============================================================
// Chem head (SIMT; fp32 on out_h)
// ============================================================
__global__ __launch_bounds__(256) void k_cp(const float* __restrict__ hfin,
        const float* __restrict__ w1, const float* __restrict__ b1,
        const float* __restrict__ w2, const float* __restrict__ b2,
        float* __restrict__ out_cp)
{
    __shared__ float As[32][36];
    __shared__ float Ws[32][132];
    __shared__ float T1[32][129];
    int tid = threadIdx.x;
    int nb = blockIdx.x * 32;
    float acc[4][4];
#pragma unroll
    for (int i = 0; i < 4; i++)
#pragma unroll
        for (int j = 0; j < 4; j++) acc[i][j] = 0.f;
    const int tx = tid & 31, ty = tid >> 5;
    const int arow = tid >> 3, ac4 = (tid & 7) * 4;
    for (int kt = 0; kt < 8; kt++) {
        int k0 = kt * 32;
        *(float4*)&As[arow][ac4] =
            *(const float4*)&hfin[(size_t)(nb + arow) * HID + k0 + ac4];
#pragma unroll
        for (int i = 0; i < 4; i++) {
            int idx = tid + 256 * i;
            int k = idx >> 5, c4 = (idx & 31) * 4;
            *(float4*)&Ws[k][c4] = *(const float4*)&w1[(size_t)(k0 + k) * 128 + c4];
        }
        __syncthreads();
#pragma unroll
        for (int kk = 0; kk < 32; kk++) {
            float a[4];
#pragma unroll
            for (int i = 0; i < 4; i++) a[i] = As[ty * 4 + i][kk];
            float4 w = *(const float4*)&Ws[kk][tx * 4];
#pragma unroll
            for (int i = 0; i < 4; i++) {
                acc[i][0] += a[i] * w.x; acc[i][1] += a[i] * w.y;
                acc[i][2] += a[i] * w.z; acc[i][3] += a[i] * w.w;
            }
        }
        __syncthreads();
    }
#pragma unroll
    for (int i = 0; i < 4; i++) {
        int e = ty * 4 + i;
#pragma unroll
        for (int j = 0; j < 4; j++) {
            int o = tx * 4 + j;
            T1[e][o] = fmaxf(acc[i][j] + __ldg(&b1[o]), 0.f);
        }
    }
    __syncthreads();

    float acc2[4] = {0.f, 0.f, 0.f, 0.f};
    const int tx2 = tid & 7, ty2 = tid >> 3;
    for (int kt = 0; kt < 4; kt++) {
        int k0 = kt * 32;
        {
            int k = tid >> 3, c4 = (tid & 7) * 4;
            *(float4*)&Ws[k][c4] = *(const float4*)&w2[(size_t)(k0 + k) * 32 + c4];
        }
        __syncthreads();
#pragma unroll
        for (int kk = 0; kk < 32; kk++) {
            float a = T1[ty2][k0 + kk];
            float4 w = *(const float4*)&Ws[kk][tx2 * 4];
            acc2[0] += a * w.x; acc2[1] += a * w.y;
            acc2[2] += a * w.z; acc2[3] += a * w.w;
        }
        __syncthreads();
    }
#pragma unroll
    for (int j = 0; j < 4; j++) {
        int o = tx2 * 4 + j;
        out_cp[(size_t)(nb + ty2) * 32 + o] = acc2[j] + __ldg(&b2[o]);
    }
}

// ============================================================
extern "C" void kernel_launch(void* const* d_in, const int* in_sizes, int n_in,
                              void* d_out, int out_size)
{
    (void)in_sizes; (void)n_in; (void)out_size;
    const float* x         = (const float*)d_in[0];
    const float* edge_attr = (const float*)d_in[1];
    const float* atom_emb  = (const float*)d_in[2];
    const float* bond_emb  = (const float*)d_in[3];
    const float* vp_w1     = (const float*)d_in[4];
    const float* vp_b1     = (const float*)d_in[5];
    const float* vp_w2     = (const float*)d_in[6];
    const float* vp_b2     = (const float*)d_in[7];
    const float* gnn_wself = (const float*)d_in[8];
    const float* gnn_bself = (const float*)d_in[9];
    const float* gnn_wmsg  = (const float*)d_in[10];
    const float* gnn_bmsg  = (const float*)d_in[11];
    const float* bc_w1     = (const float*)d_in[12];
    const float* bc_b1     = (const float*)d_in[13];
    const float* bc_w2     = (const float*)d_in[14];
    const float* bc_b2     = (const float*)d_in[15];
    const float* bc_w3     = (const float*)d_in[16];
    const float* bc_b3     = (const float*)d_in[17];
    const float* cp_w1     = (const float*)d_in[18];
    const float* cp_b1     = (const float*)d_in[19];
    const float* cp_w2     = (const float*)d_in[20];
    const float* cp_b2     = (const float*)d_in[21];
    const int* edge_index  = (const int*)d_in[22];

    float* out      = (float*)d_out;
    float* out_h    = out;                                 // [N,256]
    float* out_cp   = out_h    + (size_t)NN * HID;         // [N,32]
    float* out_vlog = out_cp   + (size_t)NN * 32;          // [N,8]
    float* out_bl   = out_vlog + (size_t)NN * 8;           // [E,4]
    float* out_viol = out_bl   + (size_t)NE * 4;           // [N]

    cudaFuncSetAttribute(k_gemm64, cudaFuncAttributeMaxDynamicSharedMemorySize, SMEM_F16);

    __half *p_h0h, *p_h1h, *p_th, *p_zh, *p_uvh;
    __half2 *p_wmsg, *p_wself, *p_bccat;
    cudaGetSymbolAddress((void**)&p_h0h,   g_h0h);
    cudaGetSymbolAddress((void**)&p_h1h,   g_h1h);
    cudaGetSymbolAddress((void**)&p_th,    g_th);
    cudaGetSymbolAddress((void**)&p_zh,    g_zh);
    cudaGetSymbolAddress((void**)&p_uvh,   g_uvh);
    cudaGetSymbolAddress((void**)&p_wmsg,  g_wmsg_h);
    cudaGetSymbolAddress((void**)&p_wself, g_wself_h);
    cudaGetSymbolAddress((void**)&p_bccat, g_bccat_h);

    const int GB = (NN + 63) / 64;            // 1563 blocks per matrix

    k_prep<<<1303, 256>>>(atom_emb, vp_w1, vp_b1, vp_w2, vp_b2,
                          gnn_wmsg, gnn_bmsg, bond_emb, gnn_wself, bc_w1);
    k_node_init<<<(NN * 32 + 255) / 256, 256>>>(x, atom_emb, out_vlog);
    k_count<<<(NE + 255) / 256, 256>>>(edge_index);
    // layer-0 dual GEMM: t0 = h0@Wmsg0, z0 = h0@Wself0   (captured by ncu)
    k_gemm64<<<2 * GB, 512, SMEM_F16>>>(p_h0h, p_wmsg, p_th, p_wself, p_zh, 3, 1);
    k_scan1<<<98, 1024>>>();
    k_scan2<<<1, 128>>>();
    k_scan3<<<98, 1024>>>(out_viol);
    k_scatter<<<(NE + 255) / 256, 256>>>(edge_index, edge_attr);

    // layer 0 aggregate: h1 = agg(z0, t0)
    k_agg<<<NN / 8, 256>>>(p_zh, p_th, gnn_bself + 0 * HID, 0, 0, out_h, p_h1h);
    // layer 1
    k_gemm64<<<2 * GB, 512, SMEM_F16>>>(p_h1h, p_wmsg + 32768, p_th,
                                        p_wself + 32768, p_zh, 8, 1);
    k_agg<<<NN / 8, 256>>>(p_zh, p_th, gnn_bself + 1 * HID, 1, 0, out_h, p_h0h);
    // layer 2 (damped: writes fp32 out_h + fp16 copy for UV GEMM)
    k_gemm64<<<2 * GB, 512, SMEM_F16>>>(p_h0h, p_wmsg + 2 * 32768, p_th,
                                        p_wself + 2 * 32768, p_zh, 8, 1);
    k_agg<<<NN / 8, 256>>>(p_zh, p_th, gnn_bself + 2 * HID, 2, 1, out_h, p_h1h);

    // bond head precompute: UV = h_final(fp16) @ [W1top|W1bot]
    k_gemm64<<<GB, 512, SMEM_F16>>>(p_h1h, p_bccat, p_uvh, nullptr, nullptr, 8, 0);

    k_bc<<<NE / 32, 256>>>(bc_w1, bc_b1, bc_w2, bc_b2, bc_w3, bc_b3,
                           edge_index, out_bl);
    k_cp<<<NN / 32, 256>>>(out_h, cp_w1, cp_b1, cp_w2, cp_b2, out_cp);
}